// round 10
// baseline (speedup 1.0000x reference)
#include <cuda_runtime.h>
#include <cuda_bf16.h>
#include <cstdint>

#define TT 2048
#define EE 2048
// N_HEADS=16, HEAD_DIM=64; q/k: 32 heads x 64, v: 16 heads x 128
// LAMBDA_INIT = 0.35550906759096927

// ---------------- device scratch ----------------
__device__ float g_q[TT * EE];
__device__ float g_k[TT * EE];
__device__ float g_v[TT * EE];
__device__ float g_o[32 * TT * 128];
__device__ float g_lam;

__device__ __nv_bfloat16 g_xh[TT * EE],  g_xl[TT * EE];
__device__ __nv_bfloat16 g_wqh[EE * EE], g_wql[EE * EE];
__device__ __nv_bfloat16 g_wkh[EE * EE], g_wkl[EE * EE];
__device__ __nv_bfloat16 g_wvh[EE * EE], g_wvl[EE * EE];
__device__ __nv_bfloat16 g_woh[EE * EE], g_wol[EE * EE];
__device__ __nv_bfloat16 g_ath[TT * EE], g_atl[TT * EE];
// attention operands (post-rope, bf16 hi/lo)
__device__ __nv_bfloat16 g_qh[TT * EE], g_ql[TT * EE];
__device__ __nv_bfloat16 g_kh[TT * EE], g_kl[TT * EE];
__device__ __nv_bfloat16 g_vh[TT * EE], g_vl[TT * EE];

// ---------------- helpers ----------------
__device__ __forceinline__ uint32_t smem_to_u32(const void* p) {
    uint32_t a;
    asm("{ .reg .u64 t; cvta.to.shared.u64 t, %1; cvt.u32.u64 %0, t; }" : "=r"(a) : "l"(p));
    return a;
}

#define CP_ASYNC16(dst, src) \
    asm volatile("cp.async.cg.shared.global [%0], [%1], 16;" :: "r"(dst), "l"(src) : "memory")
#define CP_COMMIT() asm volatile("cp.async.commit_group;" ::: "memory")
#define CP_WAIT1() asm volatile("cp.async.wait_group 1;" ::: "memory")
#define CP_WAIT0() asm volatile("cp.async.wait_group 0;" ::: "memory")

#define LDSM_X4(r0, r1, r2, r3, addr) \
    asm volatile("ldmatrix.sync.aligned.m8n8.x4.shared.b16 {%0,%1,%2,%3}, [%4];" \
                 : "=r"(r0), "=r"(r1), "=r"(r2), "=r"(r3) : "r"(addr))
#define LDSM_X4_T(r0, r1, r2, r3, addr) \
    asm volatile("ldmatrix.sync.aligned.m8n8.x4.trans.shared.b16 {%0,%1,%2,%3}, [%4];" \
                 : "=r"(r0), "=r"(r1), "=r"(r2), "=r"(r3) : "r"(addr))

#define MMA_BF16(d, a, b) \
    asm volatile("mma.sync.aligned.m16n8k16.row.col.f32.bf16.bf16.f32 " \
                 "{%0,%1,%2,%3}, {%4,%5,%6,%7}, {%8,%9}, {%0,%1,%2,%3};" \
                 : "+f"((d)[0]), "+f"((d)[1]), "+f"((d)[2]), "+f"((d)[3]) \
                 : "r"((a)[0]), "r"((a)[1]), "r"((a)[2]), "r"((a)[3]), \
                   "r"((b)[0]), "r"((b)[1]))

#define PACK_BF16X2(d, hi, lo) \
    asm("cvt.rn.bf16x2.f32 %0, %1, %2;" : "=r"(d) : "f"(hi), "f"(lo))

// fast exp2 on the FMA pipe (deg-5 poly, arg split via 1.5*2^23 trick)
__device__ __forceinline__ float fexp2f(float y) {
    y = fmaxf(y, -126.0f);
    float t = y + 12582912.0f;
    int n = __float_as_int(t) - 0x4B400000;
    float f = y - (t - 12582912.0f);
    float p = 0.0013333558f;
    p = fmaf(p, f, 0.0096181291f);
    p = fmaf(p, f, 0.0555041087f);
    p = fmaf(p, f, 0.2402264688f);
    p = fmaf(p, f, 0.6931472028f);
    p = fmaf(p, f, 1.0f);
    return __int_as_float(__float_as_int(p) + (n << 23));
}
#define LOG2E 1.4426950408889634f

// ---------------- lambda scalar ----------------
__global__ void lam_kernel(const float* __restrict__ lq1, const float* __restrict__ lk1,
                           const float* __restrict__ lq2, const float* __restrict__ lk2) {
    int t = threadIdx.x;
    float s1 = lq1[t] * lk1[t] + lq1[t + 32] * lk1[t + 32];
    float s2 = lq2[t] * lk2[t] + lq2[t + 32] * lk2[t + 32];
    #pragma unroll
    for (int o = 16; o; o >>= 1) {
        s1 += __shfl_xor_sync(~0u, s1, o);
        s2 += __shfl_xor_sync(~0u, s2, o);
    }
    if (t == 0) g_lam = __expf(s1) - __expf(s2) + 0.35550906759096927f;
}

// ---------------- fp32 -> bf16 hi/lo split ----------------
__global__ void split_kernel(const float4* __restrict__ src,
                             uint2* __restrict__ hi, uint2* __restrict__ lo) {
    int i = blockIdx.x * blockDim.x + threadIdx.x;
    float4 v = src[i];
    __nv_bfloat16 h0 = __float2bfloat16(v.x);
    __nv_bfloat16 h1 = __float2bfloat16(v.y);
    __nv_bfloat16 h2 = __float2bfloat16(v.z);
    __nv_bfloat16 h3 = __float2bfloat16(v.w);
    __nv_bfloat16 l0 = __float2bfloat16(v.x - __bfloat162float(h0));
    __nv_bfloat16 l1 = __float2bfloat16(v.y - __bfloat162float(h1));
    __nv_bfloat16 l2 = __float2bfloat16(v.z - __bfloat162float(h2));
    __nv_bfloat16 l3 = __float2bfloat16(v.w - __bfloat162float(h3));
    uint2 ho, loo;
    ho.x  = (uint32_t)__bfloat16_as_ushort(h0) | ((uint32_t)__bfloat16_as_ushort(h1) << 16);
    ho.y  = (uint32_t)__bfloat16_as_ushort(h2) | ((uint32_t)__bfloat16_as_ushort(h3) << 16);
    loo.x = (uint32_t)__bfloat16_as_ushort(l0) | ((uint32_t)__bfloat16_as_ushort(l1) << 16);
    loo.y = (uint32_t)__bfloat16_as_ushort(l2) | ((uint32_t)__bfloat16_as_ushort(l3) << 16);
    hi[i] = ho;
    lo[i] = loo;
}

// ---------------- HMMA NT GEMM core, split-bf16, 3-stage pipeline ----------------
#define ASTRIDE 40
#define BUF_BYTES (128 * ASTRIDE * 2)
#define STAGE_BYTES (4 * BUF_BYTES)        // 40960
#define GEMM_SMEM (3 * STAGE_BYTES)        // 122880

__device__ __forceinline__ void gemm_core(const __nv_bfloat16* __restrict__ Ah,
                                          const __nv_bfloat16* __restrict__ Al,
                                          const __nv_bfloat16* __restrict__ Bh,
                                          const __nv_bfloat16* __restrict__ Bl,
                                          float* __restrict__ C,
                                          uint32_t sb, int bm, int bn) {
    int tid = threadIdx.x;
    int wid = tid >> 5, l = tid & 31;
    int wm = (wid & 3) << 5;
    int wn = (wid >> 2) << 6;

    float acc[2][8][4];
    #pragma unroll
    for (int i = 0; i < 2; i++)
        #pragma unroll
        for (int j = 0; j < 8; j++)
            #pragma unroll
            for (int q = 0; q < 4; q++) acc[i][j][q] = 0.f;

    int lrow = tid >> 2;
    int lseg = (tid & 3) << 3;
    const __nv_bfloat16* srcs[4] = {Ah, Al, Bh, Bl};

    auto issue = [&](int c, int s) {
        int k0 = c << 5;
        uint32_t stage = sb + (uint32_t)s * STAGE_BYTES;
        #pragma unroll
        for (int t = 0; t < 4; t++) {
            const __nv_bfloat16* src = srcs[t];
            int rb = (t < 2) ? bm : bn;
            uint32_t db = stage + (uint32_t)t * BUF_BYTES;
            #pragma unroll
            for (int j = 0; j < 2; j++) {
                int row = lrow + (j << 6);
                const void* g = src + (size_t)(rb + row) * 2048 + k0 + lseg;
                uint32_t d = db + (uint32_t)(row * ASTRIDE + lseg) * 2;
                CP_ASYNC16(d, g);
            }
        }
        CP_COMMIT();
    };

    int a_r = l & 15;
    int a_c = (l >> 4) << 3;
    int b_r = ((l >> 4) << 3) + (l & 7);
    int b_c = ((l >> 3) & 1) << 3;

    // prologue: stages 0,1 in flight
    issue(0, 0);
    issue(1, 1);

    int sidx = 0;  // stage index of chunk c (c % 3 tracked incrementally)
    for (int c = 0; c < 64; c++) {
        // group for chunk c must be complete (chunk c+1's group may be in flight)
        CP_WAIT1();
        __syncthreads();     // all warps done reading stage (c-1)%3 -> safe to refill

        if (c + 2 < 64) {
            int s2 = sidx + 2;
            if (s2 >= 3) s2 -= 3;
            issue(c + 2, s2);
        } else {
            CP_COMMIT();     // empty group keeps wait_group accounting aligned
        }

        uint32_t stage = sb + (uint32_t)sidx * STAGE_BYTES;
        uint32_t aoff  = stage;
        uint32_t aloff = stage + BUF_BYTES;
        uint32_t bhoff = stage + 2 * BUF_BYTES;
        uint32_t bloff = stage + 3 * BUF_BYTES;

        #pragma unroll
        for (int ks = 0; ks < 2; ks++) {
            uint32_t ah[2][4], alr[2][4], bh[8][2], bl[8][2];
            #pragma unroll
            for (int i = 0; i < 2; i++) {
                uint32_t off = (uint32_t)((wm + i * 16 + a_r) * ASTRIDE + ks * 16 + a_c) * 2;
                LDSM_X4(ah[i][0], ah[i][1], ah[i][2], ah[i][3], aoff + off);
                LDSM_X4(alr[i][0], alr[i][1], alr[i][2], alr[i][3], aloff + off);
            }
            #pragma unroll
            for (int jj = 0; jj < 4; jj++) {
                uint32_t off = (uint32_t)((wn + jj * 16 + b_r) * ASTRIDE + ks * 16 + b_c) * 2;
                uint32_t r0, r1, r2, r3;
                LDSM_X4(r0, r1, r2, r3, bhoff + off);
                bh[jj * 2][0] = r0; bh[jj * 2][1] = r1;
                bh[jj * 2 + 1][0] = r2; bh[jj * 2 + 1][1] = r3;
                LDSM_X4(r0, r1, r2, r3, bloff + off);
                bl[jj * 2][0] = r0; bl[jj * 2][1] = r1;
                bl[jj * 2 + 1][0] = r2; bl[jj * 2 + 1][1] = r3;
            }
            #pragma unroll
            for (int i = 0; i < 2; i++)
                #pragma unroll
                for (int nt = 0; nt < 8; nt++) {
                    MMA_BF16(acc[i][nt], ah[i], bh[nt]);
                    MMA_BF16(acc[i][nt], alr[i], bh[nt]);
                    MMA_BF16(acc[i][nt], ah[i], bl[nt]);
                }
        }

        if (++sidx == 3) sidx = 0;
    }

    int r0q = l >> 2;
    int c0q = (l & 3) << 1;
    #pragma unroll
    for (int i = 0; i < 2; i++) {
        #pragma unroll
        for (int nt = 0; nt < 8; nt++) {
            float* base = C + (size_t)(bm + wm + i * 16 + r0q) * 2048 + bn + wn + nt * 8 + c0q;
            base[0] = acc[i][nt][0];
            base[1] = acc[i][nt][1];
            base[8 * 2048 + 0] = acc[i][nt][2];
            base[8 * 2048 + 1] = acc[i][nt][3];
        }
    }
}

// fused QKV projection: blockIdx.z selects weight/output
__global__ void __launch_bounds__(256) gemm_qkv(const __nv_bfloat16* __restrict__ xh,
                                                const __nv_bfloat16* __restrict__ xl) {
    extern __shared__ char smem[];
    uint32_t sb = smem_to_u32(smem);
    const __nv_bfloat16 *Bh, *Bl;
    float* C;
    if (blockIdx.z == 0)      { Bh = g_wqh; Bl = g_wql; C = g_q; }
    else if (blockIdx.z == 1) { Bh = g_wkh; Bl = g_wkl; C = g_k; }
    else                      { Bh = g_wvh; Bl = g_wvl; C = g_v; }
    gemm_core(xh, xl, Bh, Bl, C, sb, blockIdx.y << 7, blockIdx.x << 7);
}

// output projection
__global__ void __launch_bounds__(256) gemm_wo(float* __restrict__ out) {
    extern __shared__ char smem[];
    uint32_t sb = smem_to_u32(smem);
    gemm_core(g_ath, g_atl, g_woh, g_wol, out, sb, blockIdx.y << 7, blockIdx.x << 7);
}

// ---------------- fused RoPE + bf16 hi/lo split for q,k ----------------
__global__ void rope_split_kernel(const float* __restrict__ cosb, const float* __restrict__ sinb) {
    int idx = blockIdx.x * blockDim.x + threadIdx.x;   // 2048*32*32
    int t = idx >> 10;
    int r = idx & 1023;
    int h = r >> 5, d = r & 31;
    int base = t * 2048 + h * 64 + d;
    float c1 = cosb[t * 64 + d],      s1 = sinb[t * 64 + d];
    float c2 = cosb[t * 64 + d + 32], s2 = sinb[t * 64 + d + 32];

    float x1 = g_q[base], x2 = g_q[base + 32];
    float q1 = (x1 * c1 - x2 * s1) * 0.125f;
    float q2 = (x2 * c2 + x1 * s2) * 0.125f;
    __nv_bfloat16 h1 = __float2bfloat16(q1);
    __nv_bfloat16 h2 = __float2bfloat16(q2);
    g_qh[base] = h1;      g_ql[base]      = __float2bfloat16(q1 - __bfloat162float(h1));
    g_qh[base + 32] = h2; g_ql[base + 32] = __float2bfloat16(q2 - __bfloat162float(h2));

    x1 = g_k[base]; x2 = g_k[base + 32];
    float k1 = x1 * c1 - x2 * s1;
    float k2 = x2 * c2 + x1 * s2;
    h1 = __float2bfloat16(k1);
    h2 = __float2bfloat16(k2);
    g_kh[base] = h1;      g_kl[base]      = __float2bfloat16(k1 - __bfloat162float(h1));
    g_kh[base + 32] = h2; g_kl[base + 32] = __float2bfloat16(k2 - __bfloat162float(h2));
}

// ---------------- HMMA causal flash attention ----------------
// CTA: 128 q-rows x 1 head, 8 warps (16 rows each), kv tile 64.
#define AT_KSTR 72
#define AT_VSTR 136
#define AT_KBUF (64 * AT_KSTR * 2)         // 9216 bytes
#define AT_VBUF (64 * AT_VSTR * 2)         // 17408 bytes
#define AT_STAGE (2 * AT_KBUF + 2 * AT_VBUF)  // 53248
#define AT_QOFF (2 * AT_STAGE)             // 106496
#define AT_SMEM (AT_QOFF + 2 * 128 * AT_KSTR * 2)  // 143360

__global__ void __launch_bounds__(256, 1) attn_hmma() {
    extern __shared__ char smem[];
    uint32_t sb = smem_to_u32(smem);
    int tid = threadIdx.x;
    int w = tid >> 5, l = tid & 31;
    int qb = blockIdx.x;
    int h = blockIdx.y;
    int r0 = qb << 7;
    int p = h >> 1;
    int g = l >> 2;

    const __nv_bfloat16* qhp = g_qh + h * 64;
    const __nv_bfloat16* qlp = g_ql + h * 64;
    const __nv_bfloat16* khp = g_kh + h * 64;
    const __nv_bfloat16* klp = g_kl + h * 64;
    const __nv_bfloat16* vhp = g_vh + p * 128;
    const __nv_bfloat16* vlp = g_vl + p * 128;

    // ---- load Q tiles into smem, then ldmatrix to regs
    {
        #pragma unroll
        for (int t = 0; t < 8; t++) {
            int id = tid + (t << 8);            // 0..2047
            int tensor = id >> 10;              // 0: hi, 1: lo
            int rr = (id >> 3) & 127;
            int seg = (id & 7) << 3;
            const __nv_bfloat16* src = (tensor ? qlp : qhp) + (size_t)(r0 + rr) * 2048 + seg;
            uint4 v = *(const uint4*)src;
            *(uint4*)(smem + AT_QOFF + tensor * (128 * AT_KSTR * 2) + (rr * AT_KSTR + seg) * 2) = v;
        }
    }
    __syncthreads();

    int a_r = l & 15;
    int a_c = (l >> 4) << 3;
    uint32_t qh[4][4], ql[4][4];
    {
        uint32_t qbase = sb + AT_QOFF;
        #pragma unroll
        for (int ks = 0; ks < 4; ks++) {
            uint32_t off = (uint32_t)((w * 16 + a_r) * AT_KSTR + ks * 16 + a_c) * 2;
            LDSM_X4(qh[ks][0], qh[ks][1], qh[ks][2], qh[ks][3], qbase + off);
            LDSM_X4(ql[ks][0], ql[ks][1], ql[ks][2], ql[ks][3],
                    qbase + 128 * AT_KSTR * 2 + off);
        }
    }

    float acco[16][4];
    #pragma unroll
    for (int i = 0; i < 16; i++)
        #pragma unroll
        for (int j = 0; j < 4; j++) acco[i][j] = 0.f;
    float m0 = -1e30f, m1 = -1e30f, l0 = 0.f, l1 = 0.f;

    int nt = 2 * qb + 2;

    auto issue = [&](int j, int s) {
        int k0 = j << 6;
        uint32_t stage = sb + (uint32_t)s * AT_STAGE;
        #pragma unroll
        for (int t = 0; t < 4; t++) {        // K chunks: Kh, Kl
            int id = tid + ((t & 1) << 8);
            int rr = id >> 3, seg = (id & 7) << 3;
            const __nv_bfloat16* src = ((t >> 1) ? klp : khp) + (size_t)(k0 + rr) * 2048 + seg;
            uint32_t d = stage + (t >> 1) * AT_KBUF + (uint32_t)(rr * AT_KSTR + seg) * 2;
            CP_ASYNC16(d, src);
        }
        #pragma unroll
        for (int t = 0; t < 8; t++) {        // V chunks: Vh, Vl
            int id = tid + ((t & 3) << 8);
            int rr = id >> 4, seg = (id & 15) << 3;
            const __nv_bfloat16* src = ((t >> 2) ? vlp : vhp) + (size_t)(k0 + rr) * 2048 + seg;
            uint32_t d = stage + 2 * AT_KBUF + (t >> 2) * AT_VBUF
                       + (uint32_t)(rr * AT_VSTR + seg) * 2;
            CP_ASYNC16(d, src);
        }
        CP_COMMIT();
    };

    int b_r = ((l >> 4) << 3) + (l & 7);
    int b_c = ((l >> 3) & 1) << 3;
    int v_r = l & 15;
    int v_c = (l >> 4) << 3;
    int rw = r0 + w * 16;                     // warp's first q-row

    issue(0, 0);
    for (int j = 0; j < nt; j++) {
        int s = j & 1;
        if (j + 1 < nt) { issue(j + 1, s ^ 1); CP_WAIT1(); }
        else            { CP_WAIT0(); }
        __syncthreads();

        int k0 = j << 6;
        bool active = (k0 <= rw + 15);        // skip fully-masked warp tiles
        if (active) {
            uint32_t stage = sb + (uint32_t)s * AT_STAGE;
            uint32_t khoff = stage;
            uint32_t kloff = stage + AT_KBUF;
            uint32_t vhoff = stage + 2 * AT_KBUF;
            uint32_t vloff = stage + 2 * AT_KBUF + AT_VBUF;

            // ---- S = Q K^T (3-term split)
            float accs[8][4];
            #pragma unroll
            for (int i = 0; i < 8; i++)
                #pragma unroll
                for (int q = 0; q < 4; q++) accs[i][q] = 0.f;

            #pragma unroll
            for (int ks = 0; ks < 4; ks++) {
                uint32_t bh[8][2], bl[8][2];
                #pragma unroll
                for (int jj = 0; jj < 4; jj++) {
                    uint32_t off = (uint32_t)((jj * 16 + b_r) * AT_KSTR + ks * 16 + b_c) * 2;
                    uint32_t r0r, r1r, r2r, r3r;
                    LDSM_X4(r0r, r1r, r2r, r3r, khoff + off);
                    bh[jj * 2][0] = r0r; bh[jj * 2][1] = r1r;
                    bh[jj * 2 + 1][0] = r2r; bh[jj * 2 + 1][1] = r3r;
                    LDSM_X4(r0r, r1r, r2r, r3r, kloff + off);
                    bl[jj * 2][0] = r0r; bl[jj * 2][1] = r1r;
                    bl[jj * 2 + 1][0] = r2r; bl[jj * 2 + 1][1] = r3r;
                }
                #pragma unroll
                for (int n = 0; n < 8; n++) {
                    MMA_BF16(accs[n], qh[ks], bh[n]);
                    MMA_BF16(accs[n], ql[ks], bh[n]);
                    MMA_BF16(accs[n], qh[ks], bl[n]);
                }
            }

            // ---- causal mask (only near the diagonal)
            if (k0 + 63 > rw) {
                int rbase = rw + g;
                #pragma unroll
                for (int n = 0; n < 8; n++) {
                    int col = k0 + n * 8 + ((l & 3) << 1);
                    if (col > rbase)         accs[n][0] = -1e30f;
                    if (col + 1 > rbase)     accs[n][1] = -1e30f;
                    if (col > rbase + 8)     accs[n][2] = -1e30f;
                    if (col + 1 > rbase + 8) accs[n][3] = -1e30f;
                }
            }

            // ---- online softmax (rows g, g+8 across lane quad)
            float mx0 = -1e30f, mx1 = -1e30f;
            #pragma unroll
            for (int n = 0; n < 8; n++) {
                mx0 = fmaxf(mx0, fmaxf(accs[n][0], accs[n][1]));
                mx1 = fmaxf(mx1, fmaxf(accs[n][2], accs[n][3]));
            }
            mx0 = fmaxf(mx0, __shfl_xor_sync(~0u, mx0, 1));
            mx0 = fmaxf(mx0, __shfl_xor_sync(~0u, mx0, 2));
            mx1 = fmaxf(mx1, __shfl_xor_sync(~0u, mx1, 1));
            mx1 = fmaxf(mx1, __shfl_xor_sync(~0u, mx1, 2));
            float mn0 = fmaxf(m0, mx0), mn1 = fmaxf(m1, mx1);
            float al0 = fexp2f((m0 - mn0) * LOG2E);
            float al1 = fexp2f((m1 - mn1) * LOG2E);
            m0 = mn0; m1 = mn1;

            float sum0 = 0.f, sum1 = 0.f;
            #pragma unroll
            for (int n = 0; n < 8; n++) {
                accs[n][0] = fexp2f((accs[n][0] - mn0) * LOG2E);
                accs[n][1] = fexp2f((accs[n][1] - mn0) * LOG2E);
                accs[n][2] = fexp2f((accs[n][2] - mn1) * LOG2E);
                accs[n][3] = fexp2f((accs[n][3] - mn1) * LOG2E);
                sum0 += accs[n][0] + accs[n][1];
                sum1 += accs[n][2] + accs[n][3];
            }
            sum0 += __shfl_xor_sync(~0u, sum0, 1);
            sum0 += __shfl_xor_sync(~0u, sum0, 2);
            sum1 += __shfl_xor_sync(~0u, sum1, 1);
            sum1 += __shfl_xor_sync(~0u, sum1, 2);
            l0 = l0 * al0 + sum0;
            l1 = l1 * al1 + sum1;

            #pragma unroll
            for (int i = 0; i < 16; i++) {
                acco[i][0] *= al0; acco[i][1] *= al0;
                acco[i][2] *= al1; acco[i][3] *= al1;
            }

            // ---- P V (3-term split); P frags built straight from accs
            #pragma unroll
            for (int ks = 0; ks < 4; ks++) {
                uint32_t ph[4], pl[4];
                #pragma unroll
                for (int half = 0; half < 2; half++) {
                    float* c = accs[2 * ks + half];
                    uint32_t hb0, hb1;
                    PACK_BF16X2(hb0, c[1], c[0]);
                    PACK_BF16X2(hb1, c[3], c[2]);
                    float f0 = __int_as_float(hb0 << 16);
                    float f1 = __int_as_float(hb0 & 0xFFFF0000u);
                    float f2 = __int_as_float(hb1 << 16);
                    float f3 = __int_as_float(hb1 & 0xFFFF0000u);
                    uint32_t lb0, lb1;
                    PACK_BF16X2(lb0, c[1] - f1, c[0] - f0);
                    PACK_BF16X2(lb1, c[3] - f3, c[2] - f2);
                    ph[half * 2] = hb0; ph[half * 2 + 1] = hb1;
                    pl[half * 2] = lb0; pl[half * 2 + 1] = lb1;
                }
                uint32_t pa[4] = {ph[0], ph[1], ph[2], ph[3]};
                uint32_t pb[4] = {pl[0], pl[1], pl[2], pl[3]};
                #pragma unroll
                for (int np = 0; np < 8; np++) {
                    uint32_t off = (uint32_t)((ks * 16 + v_r) * AT_VSTR + np * 16 + v_c) * 2;
                    uint32_t vh0, vh1, vh2, vh3, vl0, vl1, vl2, vl3;
                    LDSM_X4_T(vh0, vh1, vh2, vh3, vhoff + off);
                    LDSM_X4_T(vl0, vl1, vl2, vl3, vloff + off);
                    uint32_t b0[2] = {vh0, vh1}, b1[2] = {vh2, vh3};
                    uint32_t c0[2] = {vl0, vl1}, c1[2] = {vl2, vl3};
                    MMA_BF16(acco[2 * np],     pa, b0);
                    MMA_BF16(acco[2 * np],     pb, b0);
                    MMA_BF16(acco[2 * np],     pa, c0);
                    MMA_BF16(acco[2 * np + 1], pa, b1);
                    MMA_BF16(acco[2 * np + 1], pb, b1);
                    MMA_BF16(acco[2 * np + 1], pa, c1);
                }
            }
        }
        __syncthreads();
    }

    // ---- epilogue
    float inv0 = 1.0f / l0, inv1 = 1.0f / l1;
    int rbase = rw + g;
    #pragma unroll
    for (int vt = 0; vt < 16; vt++) {
        int col = vt * 8 + ((l & 3) << 1);
        float* d0 = g_o + ((size_t)h * 2048 + rbase) * 128 + col;
        float* d1 = g_o + ((size_t)h * 2048 + rbase + 8) * 128 + col;
        *(float2*)d0 = make_float2(acco[vt][0] * inv0, acco[vt][1] * inv0);
        *(float2*)d1 = make_float2(acco[vt][2] * inv1, acco[vt][3] * inv1);
    }
}

// ---------------- combine + RMSNorm -> bf16 hi/lo directly ----------------
__global__ void combine_kernel(const float* __restrict__ subln) {
    int t = blockIdx.x;
    int tid = threadIdx.x;
    int p = tid >> 4, lane = tid & 15;
    int d = lane << 3;
    const float* o0 = g_o + ((size_t)(2 * p) * TT + t) * 128 + d;
    const float* o1 = g_o + ((size_t)(2 * p + 1) * TT + t) * 128 + d;
    float lam = g_lam;
    float4 a0 = *(const float4*)&o0[0], a1 = *(const float4*)&o0[4];
    float4 b0 = *(const float4*)&o1[0], b1 = *(const float4*)&o1[4];
    float c[8];
    c[0] = a0.x - lam * b0.x; c[1] = a0.y - lam * b0.y;
    c[2] = a0.z - lam * b0.z; c[3] = a0.w - lam * b0.w;
    c[4] = a1.x - lam * b1.x; c[5] = a1.y - lam * b1.y;
    c[6] = a1.z - lam * b1.z; c[7] = a1.w - lam * b1.w;
    float ss = 0.f;
    #pragma unroll
    for (int i = 0; i < 8; i++) ss += c[i] * c[i];
    ss += __shfl_xor_sync(~0u, ss, 8);
    ss += __shfl_xor_sync(~0u, ss, 4);
    ss += __shfl_xor_sync(~0u, ss, 2);
    ss += __shfl_xor_sync(~0u, ss, 1);
    float rinv = rsqrtf(ss * (1.0f / 128.0f) + 1e-5f) * 0.6444909324090307f;

    uint32_t hv[4], lv[4];
    #pragma unroll
    for (int i = 0; i < 4; i++) {
        float v0 = c[2 * i] * rinv * subln[d + 2 * i];
        float v1 = c[2 * i + 1] * rinv * subln[d + 2 * i + 1];
        uint32_t hb;
        PACK_BF16X2(hb, v1, v0);
        float f0 = __int_as_float(hb << 16);
        float f1 = __int_as_float(hb & 0xFFFF0000u);
        uint32_t lb;
        PACK_BF16X2(lb, v1 - f1, v0 - f0);
        hv[i] = hb;
        lv[i] = lb;
    }
    size_t off = (size_t)t * 2048 + p * 128 + d;
    *(uint4*)(g_ath + off) = make_uint4(hv[0], hv[1], hv[2], hv[3]);
    *(uint4*)(g_atl + off) = make_uint4(lv[0], lv[1], lv[2], lv[3]);
}

// ---------------- launch ----------------
extern "C" void kernel_launch(void* const* d_in, const int* in_sizes, int n_in,
                              void* d_out, int out_size) {
    (void)in_sizes; (void)n_in; (void)out_size;
    const float* x     = (const float*)d_in[0];
    const float* cosb  = (const float*)d_in[1];
    const float* sinb  = (const float*)d_in[2];
    const float* Wq    = (const float*)d_in[3];
    const float* Wk    = (const float*)d_in[4];
    const float* Wv    = (const float*)d_in[5];
    const float* Wo    = (const float*)d_in[6];
    const float* lq1   = (const float*)d_in[7];
    const float* lk1   = (const float*)d_in[8];
    const float* lq2   = (const float*)d_in[9];
    const float* lk2   = (const float*)d_in[10];
    const float* subln = (const float*)d_in[11];
    float* out = (float*)d_out;

    float* vp;
    __nv_bfloat16 *xh, *xl, *wqh, *wql, *wkh, *wkl, *wvh, *wvl, *woh, *wol, *vhh, *vll;
    cudaGetSymbolAddress((void**)&vp, g_v);
    cudaGetSymbolAddress((void**)&xh, g_xh);   cudaGetSymbolAddress((void**)&xl, g_xl);
    cudaGetSymbolAddress((void**)&wqh, g_wqh); cudaGetSymbolAddress((void**)&wql, g_wql);
    cudaGetSymbolAddress((void**)&wkh, g_wkh); cudaGetSymbolAddress((void**)&wkl, g_wkl);
    cudaGetSymbolAddress((void**)&wvh, g_wvh); cudaGetSymbolAddress((void**)&wvl, g_wvl);
    cudaGetSymbolAddress((void**)&woh, g_woh); cudaGetSymbolAddress((void**)&wol, g_wol);
    cudaGetSymbolAddress((void**)&vhh, g_vh);  cudaGetSymbolAddress((void**)&vll, g_vl);

    cudaFuncSetAttribute(gemm_qkv, cudaFuncAttributeMaxDynamicSharedMemorySize, GEMM_SMEM);
    cudaFuncSetAttribute(gemm_wo,  cudaFuncAttributeMaxDynamicSharedMemorySize, GEMM_SMEM);
    cudaFuncSetAttribute(attn_hmma, cudaFuncAttributeMaxDynamicSharedMemorySize, AT_SMEM);

    lam_kernel<<<1, 32>>>(lq1, lk1, lq2, lk2);

    const int SG = (TT * EE / 4) / 256;
    split_kernel<<<SG, 256>>>((const float4*)x,  (uint2*)xh,  (uint2*)xl);
    split_kernel<<<SG, 256>>>((const float4*)Wq, (uint2*)wqh, (uint2*)wql);
    split_kernel<<<SG, 256>>>((const float4*)Wk, (uint2*)wkh, (uint2*)wkl);
    split_kernel<<<SG, 256>>>((const float4*)Wv, (uint2*)wvh, (uint2*)wvl);
    split_kernel<<<SG, 256>>>((const float4*)Wo, (uint2*)woh, (uint2*)wol);

    gemm_qkv<<<dim3(16, 16, 3), 256, GEMM_SMEM>>>(xh, xl);

    rope_split_kernel<<<8192, 256>>>(cosb, sinb);
    split_kernel<<<SG, 256>>>((const float4*)vp, (uint2*)vhh, (uint2*)vll);

    attn_hmma<<<dim3(16, 32), 256, AT_SMEM>>>();

    combine_kernel<<<TT, 256>>>(subln);

    gemm_wo<<<dim3(16, 16), 256, GEMM_SMEM>>>(out);
}

// round 11
// speedup vs baseline: 1.1009x; 1.1009x over previous
#include <cuda_runtime.h>
#include <cuda_bf16.h>
#include <cstdint>

#define TT 2048
#define EE 2048
// N_HEADS=16, HEAD_DIM=64; q/k: 32 heads x 64, v: 16 heads x 128
// LAMBDA_INIT = 0.35550906759096927

// ---------------- device scratch ----------------
__device__ float g_q[TT * EE];
__device__ float g_k[TT * EE];
__device__ float g_v[TT * EE];
__device__ float g_o[32 * TT * 128];
__device__ float g_lam;

__device__ __nv_bfloat16 g_xh[TT * EE],  g_xl[TT * EE];
__device__ __nv_bfloat16 g_wqh[EE * EE], g_wql[EE * EE];
__device__ __nv_bfloat16 g_wkh[EE * EE], g_wkl[EE * EE];
__device__ __nv_bfloat16 g_wvh[EE * EE], g_wvl[EE * EE];
__device__ __nv_bfloat16 g_woh[EE * EE], g_wol[EE * EE];
__device__ __nv_bfloat16 g_ath[TT * EE], g_atl[TT * EE];
// attention operands (post-rope, bf16 hi/lo)
__device__ __nv_bfloat16 g_qh[TT * EE], g_ql[TT * EE];
__device__ __nv_bfloat16 g_kh[TT * EE], g_kl[TT * EE];
__device__ __nv_bfloat16 g_vh[TT * EE], g_vl[TT * EE];

// ---------------- helpers ----------------
__device__ __forceinline__ uint32_t smem_to_u32(const void* p) {
    uint32_t a;
    asm("{ .reg .u64 t; cvta.to.shared.u64 t, %1; cvt.u32.u64 %0, t; }" : "=r"(a) : "l"(p));
    return a;
}

#define CP_ASYNC16(dst, src) \
    asm volatile("cp.async.cg.shared.global [%0], [%1], 16;" :: "r"(dst), "l"(src) : "memory")
#define CP_COMMIT() asm volatile("cp.async.commit_group;" ::: "memory")
#define CP_WAIT1() asm volatile("cp.async.wait_group 1;" ::: "memory")
#define CP_WAIT0() asm volatile("cp.async.wait_group 0;" ::: "memory")

#define LDSM_X4(r0, r1, r2, r3, addr) \
    asm volatile("ldmatrix.sync.aligned.m8n8.x4.shared.b16 {%0,%1,%2,%3}, [%4];" \
                 : "=r"(r0), "=r"(r1), "=r"(r2), "=r"(r3) : "r"(addr))
#define LDSM_X4_T(r0, r1, r2, r3, addr) \
    asm volatile("ldmatrix.sync.aligned.m8n8.x4.trans.shared.b16 {%0,%1,%2,%3}, [%4];" \
                 : "=r"(r0), "=r"(r1), "=r"(r2), "=r"(r3) : "r"(addr))

#define MMA_BF16(d, a, b) \
    asm volatile("mma.sync.aligned.m16n8k16.row.col.f32.bf16.bf16.f32 " \
                 "{%0,%1,%2,%3}, {%4,%5,%6,%7}, {%8,%9}, {%0,%1,%2,%3};" \
                 : "+f"((d)[0]), "+f"((d)[1]), "+f"((d)[2]), "+f"((d)[3]) \
                 : "r"((a)[0]), "r"((a)[1]), "r"((a)[2]), "r"((a)[3]), \
                   "r"((b)[0]), "r"((b)[1]))

#define PACK_BF16X2(d, hi, lo) \
    asm("cvt.rn.bf16x2.f32 %0, %1, %2;" : "=r"(d) : "f"(hi), "f"(lo))

// fast exp2 on the FMA pipe (deg-5 poly, arg split via 1.5*2^23 trick)
__device__ __forceinline__ float fexp2f(float y) {
    y = fmaxf(y, -126.0f);
    float t = y + 12582912.0f;
    int n = __float_as_int(t) - 0x4B400000;
    float f = y - (t - 12582912.0f);
    float p = 0.0013333558f;
    p = fmaf(p, f, 0.0096181291f);
    p = fmaf(p, f, 0.0555041087f);
    p = fmaf(p, f, 0.2402264688f);
    p = fmaf(p, f, 0.6931472028f);
    p = fmaf(p, f, 1.0f);
    return __int_as_float(__float_as_int(p) + (n << 23));
}
#define LOG2E 1.4426950408889634f

// ---------------- lambda scalar ----------------
__global__ void lam_kernel(const float* __restrict__ lq1, const float* __restrict__ lk1,
                           const float* __restrict__ lq2, const float* __restrict__ lk2) {
    int t = threadIdx.x;
    float s1 = lq1[t] * lk1[t] + lq1[t + 32] * lk1[t + 32];
    float s2 = lq2[t] * lk2[t] + lq2[t + 32] * lk2[t + 32];
    #pragma unroll
    for (int o = 16; o; o >>= 1) {
        s1 += __shfl_xor_sync(~0u, s1, o);
        s2 += __shfl_xor_sync(~0u, s2, o);
    }
    if (t == 0) g_lam = __expf(s1) - __expf(s2) + 0.35550906759096927f;
}

// ---------------- fp32 -> bf16 hi/lo split ----------------
__global__ void split_kernel(const float4* __restrict__ src,
                             uint2* __restrict__ hi, uint2* __restrict__ lo) {
    int i = blockIdx.x * blockDim.x + threadIdx.x;
    float4 v = src[i];
    __nv_bfloat16 h0 = __float2bfloat16(v.x);
    __nv_bfloat16 h1 = __float2bfloat16(v.y);
    __nv_bfloat16 h2 = __float2bfloat16(v.z);
    __nv_bfloat16 h3 = __float2bfloat16(v.w);
    __nv_bfloat16 l0 = __float2bfloat16(v.x - __bfloat162float(h0));
    __nv_bfloat16 l1 = __float2bfloat16(v.y - __bfloat162float(h1));
    __nv_bfloat16 l2 = __float2bfloat16(v.z - __bfloat162float(h2));
    __nv_bfloat16 l3 = __float2bfloat16(v.w - __bfloat162float(h3));
    uint2 ho, loo;
    ho.x  = (uint32_t)__bfloat16_as_ushort(h0) | ((uint32_t)__bfloat16_as_ushort(h1) << 16);
    ho.y  = (uint32_t)__bfloat16_as_ushort(h2) | ((uint32_t)__bfloat16_as_ushort(h3) << 16);
    loo.x = (uint32_t)__bfloat16_as_ushort(l0) | ((uint32_t)__bfloat16_as_ushort(l1) << 16);
    loo.y = (uint32_t)__bfloat16_as_ushort(l2) | ((uint32_t)__bfloat16_as_ushort(l3) << 16);
    hi[i] = ho;
    lo[i] = loo;
}

// ---------------- HMMA NT GEMM core, split-bf16, 2-stage, 2 CTAs/SM ----------------
#define ASTRIDE 40
#define BUF_BYTES (128 * ASTRIDE * 2)
#define STAGE_BYTES (4 * BUF_BYTES)        // 40960
#define GEMM_SMEM (2 * STAGE_BYTES)        // 81920  (2 CTAs x 80KB = 160KB <= 227KB)

__device__ __forceinline__ void gemm_core(const __nv_bfloat16* __restrict__ Ah,
                                          const __nv_bfloat16* __restrict__ Al,
                                          const __nv_bfloat16* __restrict__ Bh,
                                          const __nv_bfloat16* __restrict__ Bl,
                                          float* __restrict__ C,
                                          uint32_t sb, int bm, int bn) {
    int tid = threadIdx.x;
    int wid = tid >> 5, l = tid & 31;
    int wm = (wid & 3) << 5;
    int wn = (wid >> 2) << 6;

    float acc[2][8][4];
    #pragma unroll
    for (int i = 0; i < 2; i++)
        #pragma unroll
        for (int j = 0; j < 8; j++)
            #pragma unroll
            for (int q = 0; q < 4; q++) acc[i][j][q] = 0.f;

    int lrow = tid >> 2;
    int lseg = (tid & 3) << 3;
    const __nv_bfloat16* srcs[4] = {Ah, Al, Bh, Bl};

    auto issue = [&](int c, int s) {
        int k0 = c << 5;
        uint32_t stage = sb + (uint32_t)s * STAGE_BYTES;
        #pragma unroll
        for (int t = 0; t < 4; t++) {
            const __nv_bfloat16* src = srcs[t];
            int rb = (t < 2) ? bm : bn;
            uint32_t db = stage + (uint32_t)t * BUF_BYTES;
            #pragma unroll
            for (int j = 0; j < 2; j++) {
                int row = lrow + (j << 6);
                const void* g = src + (size_t)(rb + row) * 2048 + k0 + lseg;
                uint32_t d = db + (uint32_t)(row * ASTRIDE + lseg) * 2;
                CP_ASYNC16(d, g);
            }
        }
        CP_COMMIT();
    };

    int a_r = l & 15;
    int a_c = (l >> 4) << 3;
    int b_r = ((l >> 4) << 3) + (l & 7);
    int b_c = ((l >> 3) & 1) << 3;

    issue(0, 0);
    for (int c = 0; c < 64; c++) {
        int s = c & 1;
        if (c + 1 < 64) { issue(c + 1, s ^ 1); CP_WAIT1(); }
        else            { CP_WAIT0(); }
        __syncthreads();

        uint32_t stage = sb + (uint32_t)s * STAGE_BYTES;
        uint32_t aoff  = stage;
        uint32_t aloff = stage + BUF_BYTES;
        uint32_t bhoff = stage + 2 * BUF_BYTES;
        uint32_t bloff = stage + 3 * BUF_BYTES;

        #pragma unroll
        for (int ks = 0; ks < 2; ks++) {
            uint32_t ah[2][4], alr[2][4], bh[8][2], bl[8][2];
            #pragma unroll
            for (int i = 0; i < 2; i++) {
                uint32_t off = (uint32_t)((wm + i * 16 + a_r) * ASTRIDE + ks * 16 + a_c) * 2;
                LDSM_X4(ah[i][0], ah[i][1], ah[i][2], ah[i][3], aoff + off);
                LDSM_X4(alr[i][0], alr[i][1], alr[i][2], alr[i][3], aloff + off);
            }
            #pragma unroll
            for (int jj = 0; jj < 4; jj++) {
                uint32_t off = (uint32_t)((wn + jj * 16 + b_r) * ASTRIDE + ks * 16 + b_c) * 2;
                uint32_t r0, r1, r2, r3;
                LDSM_X4(r0, r1, r2, r3, bhoff + off);
                bh[jj * 2][0] = r0; bh[jj * 2][1] = r1;
                bh[jj * 2 + 1][0] = r2; bh[jj * 2 + 1][1] = r3;
                LDSM_X4(r0, r1, r2, r3, bloff + off);
                bl[jj * 2][0] = r0; bl[jj * 2][1] = r1;
                bl[jj * 2 + 1][0] = r2; bl[jj * 2 + 1][1] = r3;
            }
            #pragma unroll
            for (int i = 0; i < 2; i++)
                #pragma unroll
                for (int nt = 0; nt < 8; nt++) {
                    MMA_BF16(acc[i][nt], ah[i], bh[nt]);
                    MMA_BF16(acc[i][nt], alr[i], bh[nt]);
                    MMA_BF16(acc[i][nt], ah[i], bl[nt]);
                }
        }
        __syncthreads();
    }

    int r0q = l >> 2;
    int c0q = (l & 3) << 1;
    #pragma unroll
    for (int i = 0; i < 2; i++) {
        #pragma unroll
        for (int nt = 0; nt < 8; nt++) {
            float* base = C + (size_t)(bm + wm + i * 16 + r0q) * 2048 + bn + wn + nt * 8 + c0q;
            base[0] = acc[i][nt][0];
            base[1] = acc[i][nt][1];
            base[8 * 2048 + 0] = acc[i][nt][2];
            base[8 * 2048 + 1] = acc[i][nt][3];
        }
    }
}

// fused QKV projection: blockIdx.z selects weight/output. 2 CTAs/SM target.
__global__ void __launch_bounds__(256, 2) gemm_qkv(const __nv_bfloat16* __restrict__ xh,
                                                   const __nv_bfloat16* __restrict__ xl) {
    extern __shared__ char smem[];
    uint32_t sb = smem_to_u32(smem);
    const __nv_bfloat16 *Bh, *Bl;
    float* C;
    if (blockIdx.z == 0)      { Bh = g_wqh; Bl = g_wql; C = g_q; }
    else if (blockIdx.z == 1) { Bh = g_wkh; Bl = g_wkl; C = g_k; }
    else                      { Bh = g_wvh; Bl = g_wvl; C = g_v; }
    gemm_core(xh, xl, Bh, Bl, C, sb, blockIdx.y << 7, blockIdx.x << 7);
}

// output projection
__global__ void __launch_bounds__(256, 2) gemm_wo(float* __restrict__ out) {
    extern __shared__ char smem[];
    uint32_t sb = smem_to_u32(smem);
    gemm_core(g_ath, g_atl, g_woh, g_wol, out, sb, blockIdx.y << 7, blockIdx.x << 7);
}

// ---------------- fused RoPE + bf16 hi/lo split for q,k ----------------
__global__ void rope_split_kernel(const float* __restrict__ cosb, const float* __restrict__ sinb) {
    int idx = blockIdx.x * blockDim.x + threadIdx.x;   // 2048*32*32
    int t = idx >> 10;
    int r = idx & 1023;
    int h = r >> 5, d = r & 31;
    int base = t * 2048 + h * 64 + d;
    float c1 = cosb[t * 64 + d],      s1 = sinb[t * 64 + d];
    float c2 = cosb[t * 64 + d + 32], s2 = sinb[t * 64 + d + 32];

    float x1 = g_q[base], x2 = g_q[base + 32];
    float q1 = (x1 * c1 - x2 * s1) * 0.125f;
    float q2 = (x2 * c2 + x1 * s2) * 0.125f;
    __nv_bfloat16 h1 = __float2bfloat16(q1);
    __nv_bfloat16 h2 = __float2bfloat16(q2);
    g_qh[base] = h1;      g_ql[base]      = __float2bfloat16(q1 - __bfloat162float(h1));
    g_qh[base + 32] = h2; g_ql[base + 32] = __float2bfloat16(q2 - __bfloat162float(h2));

    x1 = g_k[base]; x2 = g_k[base + 32];
    float k1 = x1 * c1 - x2 * s1;
    float k2 = x2 * c2 + x1 * s2;
    h1 = __float2bfloat16(k1);
    h2 = __float2bfloat16(k2);
    g_kh[base] = h1;      g_kl[base]      = __float2bfloat16(k1 - __bfloat162float(h1));
    g_kh[base + 32] = h2; g_kl[base + 32] = __float2bfloat16(k2 - __bfloat162float(h2));
}

// ---------------- HMMA causal flash attention ----------------
// CTA: 128 q-rows x 1 head, 8 warps (16 rows each), kv tile 64.
#define AT_KSTR 72
#define AT_VSTR 136
#define AT_KBUF (64 * AT_KSTR * 2)         // 9216 bytes
#define AT_VBUF (64 * AT_VSTR * 2)         // 17408 bytes
#define AT_STAGE (2 * AT_KBUF + 2 * AT_VBUF)  // 53248
#define AT_QOFF (2 * AT_STAGE)             // 106496
#define AT_SMEM (AT_QOFF + 2 * 128 * AT_KSTR * 2)  // 143360

__global__ void __launch_bounds__(256, 1) attn_hmma() {
    extern __shared__ char smem[];
    uint32_t sb = smem_to_u32(smem);
    int tid = threadIdx.x;
    int w = tid >> 5, l = tid & 31;
    int qb = blockIdx.x;
    int h = blockIdx.y;
    int r0 = qb << 7;
    int p = h >> 1;
    int g = l >> 2;

    const __nv_bfloat16* qhp = g_qh + h * 64;
    const __nv_bfloat16* qlp = g_ql + h * 64;
    const __nv_bfloat16* khp = g_kh + h * 64;
    const __nv_bfloat16* klp = g_kl + h * 64;
    const __nv_bfloat16* vhp = g_vh + p * 128;
    const __nv_bfloat16* vlp = g_vl + p * 128;

    // ---- load Q tiles into smem, then ldmatrix to regs
    {
        #pragma unroll
        for (int t = 0; t < 8; t++) {
            int id = tid + (t << 8);            // 0..2047
            int tensor = id >> 10;              // 0: hi, 1: lo
            int rr = (id >> 3) & 127;
            int seg = (id & 7) << 3;
            const __nv_bfloat16* src = (tensor ? qlp : qhp) + (size_t)(r0 + rr) * 2048 + seg;
            uint4 v = *(const uint4*)src;
            *(uint4*)(smem + AT_QOFF + tensor * (128 * AT_KSTR * 2) + (rr * AT_KSTR + seg) * 2) = v;
        }
    }
    __syncthreads();

    int a_r = l & 15;
    int a_c = (l >> 4) << 3;
    uint32_t qh[4][4], ql[4][4];
    {
        uint32_t qbase = sb + AT_QOFF;
        #pragma unroll
        for (int ks = 0; ks < 4; ks++) {
            uint32_t off = (uint32_t)((w * 16 + a_r) * AT_KSTR + ks * 16 + a_c) * 2;
            LDSM_X4(qh[ks][0], qh[ks][1], qh[ks][2], qh[ks][3], qbase + off);
            LDSM_X4(ql[ks][0], ql[ks][1], ql[ks][2], ql[ks][3],
                    qbase + 128 * AT_KSTR * 2 + off);
        }
    }

    float acco[16][4];
    #pragma unroll
    for (int i = 0; i < 16; i++)
        #pragma unroll
        for (int j = 0; j < 4; j++) acco[i][j] = 0.f;
    float m0 = -1e30f, m1 = -1e30f, l0 = 0.f, l1 = 0.f;

    int nt = 2 * qb + 2;

    auto issue = [&](int j, int s) {
        int k0 = j << 6;
        uint32_t stage = sb + (uint32_t)s * AT_STAGE;
        #pragma unroll
        for (int t = 0; t < 4; t++) {        // K chunks: Kh, Kl
            int id = tid + ((t & 1) << 8);
            int rr = id >> 3, seg = (id & 7) << 3;
            const __nv_bfloat16* src = ((t >> 1) ? klp : khp) + (size_t)(k0 + rr) * 2048 + seg;
            uint32_t d = stage + (t >> 1) * AT_KBUF + (uint32_t)(rr * AT_KSTR + seg) * 2;
            CP_ASYNC16(d, src);
        }
        #pragma unroll
        for (int t = 0; t < 8; t++) {        // V chunks: Vh, Vl
            int id = tid + ((t & 3) << 8);
            int rr = id >> 4, seg = (id & 15) << 3;
            const __nv_bfloat16* src = ((t >> 2) ? vlp : vhp) + (size_t)(k0 + rr) * 2048 + seg;
            uint32_t d = stage + 2 * AT_KBUF + (t >> 2) * AT_VBUF
                       + (uint32_t)(rr * AT_VSTR + seg) * 2;
            CP_ASYNC16(d, src);
        }
        CP_COMMIT();
    };

    int b_r = ((l >> 4) << 3) + (l & 7);
    int b_c = ((l >> 3) & 1) << 3;
    int v_r = l & 15;
    int v_c = (l >> 4) << 3;
    int rw = r0 + w * 16;                     // warp's first q-row

    issue(0, 0);
    for (int j = 0; j < nt; j++) {
        int s = j & 1;
        if (j + 1 < nt) { issue(j + 1, s ^ 1); CP_WAIT1(); }
        else            { CP_WAIT0(); }
        __syncthreads();

        int k0 = j << 6;
        bool active = (k0 <= rw + 15);        // skip fully-masked warp tiles
        if (active) {
            uint32_t stage = sb + (uint32_t)s * AT_STAGE;
            uint32_t khoff = stage;
            uint32_t kloff = stage + AT_KBUF;
            uint32_t vhoff = stage + 2 * AT_KBUF;
            uint32_t vloff = stage + 2 * AT_KBUF + AT_VBUF;

            // ---- S = Q K^T (3-term split)
            float accs[8][4];
            #pragma unroll
            for (int i = 0; i < 8; i++)
                #pragma unroll
                for (int q = 0; q < 4; q++) accs[i][q] = 0.f;

            #pragma unroll
            for (int ks = 0; ks < 4; ks++) {
                uint32_t bh[8][2], bl[8][2];
                #pragma unroll
                for (int jj = 0; jj < 4; jj++) {
                    uint32_t off = (uint32_t)((jj * 16 + b_r) * AT_KSTR + ks * 16 + b_c) * 2;
                    uint32_t r0r, r1r, r2r, r3r;
                    LDSM_X4(r0r, r1r, r2r, r3r, khoff + off);
                    bh[jj * 2][0] = r0r; bh[jj * 2][1] = r1r;
                    bh[jj * 2 + 1][0] = r2r; bh[jj * 2 + 1][1] = r3r;
                    LDSM_X4(r0r, r1r, r2r, r3r, kloff + off);
                    bl[jj * 2][0] = r0r; bl[jj * 2][1] = r1r;
                    bl[jj * 2 + 1][0] = r2r; bl[jj * 2 + 1][1] = r3r;
                }
                #pragma unroll
                for (int n = 0; n < 8; n++) {
                    MMA_BF16(accs[n], qh[ks], bh[n]);
                    MMA_BF16(accs[n], ql[ks], bh[n]);
                    MMA_BF16(accs[n], qh[ks], bl[n]);
                }
            }

            // ---- causal mask (only near the diagonal)
            if (k0 + 63 > rw) {
                int rbase = rw + g;
                #pragma unroll
                for (int n = 0; n < 8; n++) {
                    int col = k0 + n * 8 + ((l & 3) << 1);
                    if (col > rbase)         accs[n][0] = -1e30f;
                    if (col + 1 > rbase)     accs[n][1] = -1e30f;
                    if (col > rbase + 8)     accs[n][2] = -1e30f;
                    if (col + 1 > rbase + 8) accs[n][3] = -1e30f;
                }
            }

            // ---- online softmax (rows g, g+8 across lane quad)
            float mx0 = -1e30f, mx1 = -1e30f;
            #pragma unroll
            for (int n = 0; n < 8; n++) {
                mx0 = fmaxf(mx0, fmaxf(accs[n][0], accs[n][1]));
                mx1 = fmaxf(mx1, fmaxf(accs[n][2], accs[n][3]));
            }
            mx0 = fmaxf(mx0, __shfl_xor_sync(~0u, mx0, 1));
            mx0 = fmaxf(mx0, __shfl_xor_sync(~0u, mx0, 2));
            mx1 = fmaxf(mx1, __shfl_xor_sync(~0u, mx1, 1));
            mx1 = fmaxf(mx1, __shfl_xor_sync(~0u, mx1, 2));
            float mn0 = fmaxf(m0, mx0), mn1 = fmaxf(m1, mx1);
            float al0 = fexp2f((m0 - mn0) * LOG2E);
            float al1 = fexp2f((m1 - mn1) * LOG2E);
            m0 = mn0; m1 = mn1;

            float sum0 = 0.f, sum1 = 0.f;
            #pragma unroll
            for (int n = 0; n < 8; n++) {
                accs[n][0] = fexp2f((accs[n][0] - mn0) * LOG2E);
                accs[n][1] = fexp2f((accs[n][1] - mn0) * LOG2E);
                accs[n][2] = fexp2f((accs[n][2] - mn1) * LOG2E);
                accs[n][3] = fexp2f((accs[n][3] - mn1) * LOG2E);
                sum0 += accs[n][0] + accs[n][1];
                sum1 += accs[n][2] + accs[n][3];
            }
            sum0 += __shfl_xor_sync(~0u, sum0, 1);
            sum0 += __shfl_xor_sync(~0u, sum0, 2);
            sum1 += __shfl_xor_sync(~0u, sum1, 1);
            sum1 += __shfl_xor_sync(~0u, sum1, 2);
            l0 = l0 * al0 + sum0;
            l1 = l1 * al1 + sum1;

            #pragma unroll
            for (int i = 0; i < 16; i++) {
                acco[i][0] *= al0; acco[i][1] *= al0;
                acco[i][2] *= al1; acco[i][3] *= al1;
            }

            // ---- P V (3-term split); P frags built straight from accs
            #pragma unroll
            for (int ks = 0; ks < 4; ks++) {
                uint32_t ph[4], pl[4];
                #pragma unroll
                for (int half = 0; half < 2; half++) {
                    float* c = accs[2 * ks + half];
                    uint32_t hb0, hb1;
                    PACK_BF16X2(hb0, c[1], c[0]);
                    PACK_BF16X2(hb1, c[3], c[2]);
                    float f0 = __int_as_float(hb0 << 16);
                    float f1 = __int_as_float(hb0 & 0xFFFF0000u);
                    float f2 = __int_as_float(hb1 << 16);
                    float f3 = __int_as_float(hb1 & 0xFFFF0000u);
                    uint32_t lb0, lb1;
                    PACK_BF16X2(lb0, c[1] - f1, c[0] - f0);
                    PACK_BF16X2(lb1, c[3] - f3, c[2] - f2);
                    ph[half * 2] = hb0; ph[half * 2 + 1] = hb1;
                    pl[half * 2] = lb0; pl[half * 2 + 1] = lb1;
                }
                uint32_t pa[4] = {ph[0], ph[1], ph[2], ph[3]};
                uint32_t pb[4] = {pl[0], pl[1], pl[2], pl[3]};
                #pragma unroll
                for (int np = 0; np < 8; np++) {
                    uint32_t off = (uint32_t)((ks * 16 + v_r) * AT_VSTR + np * 16 + v_c) * 2;
                    uint32_t vh0, vh1, vh2, vh3, vl0, vl1, vl2, vl3;
                    LDSM_X4_T(vh0, vh1, vh2, vh3, vhoff + off);
                    LDSM_X4_T(vl0, vl1, vl2, vl3, vloff + off);
                    uint32_t b0[2] = {vh0, vh1}, b1[2] = {vh2, vh3};
                    uint32_t c0[2] = {vl0, vl1}, c1[2] = {vl2, vl3};
                    MMA_BF16(acco[2 * np],     pa, b0);
                    MMA_BF16(acco[2 * np],     pb, b0);
                    MMA_BF16(acco[2 * np],     pa, c0);
                    MMA_BF16(acco[2 * np + 1], pa, b1);
                    MMA_BF16(acco[2 * np + 1], pb, b1);
                    MMA_BF16(acco[2 * np + 1], pa, c1);
                }
            }
        }
        __syncthreads();
    }

    // ---- epilogue
    float inv0 = 1.0f / l0, inv1 = 1.0f / l1;
    int rbase = rw + g;
    #pragma unroll
    for (int vt = 0; vt < 16; vt++) {
        int col = vt * 8 + ((l & 3) << 1);
        float* d0 = g_o + ((size_t)h * 2048 + rbase) * 128 + col;
        float* d1 = g_o + ((size_t)h * 2048 + rbase + 8) * 128 + col;
        *(float2*)d0 = make_float2(acco[vt][0] * inv0, acco[vt][1] * inv0);
        *(float2*)d1 = make_float2(acco[vt][2] * inv1, acco[vt][3] * inv1);
    }
}

// ---------------- combine + RMSNorm -> bf16 hi/lo directly ----------------
__global__ void combine_kernel(const float* __restrict__ subln) {
    int t = blockIdx.x;
    int tid = threadIdx.x;
    int p = tid >> 4, lane = tid & 15;
    int d = lane << 3;
    const float* o0 = g_o + ((size_t)(2 * p) * TT + t) * 128 + d;
    const float* o1 = g_o + ((size_t)(2 * p + 1) * TT + t) * 128 + d;
    float lam = g_lam;
    float4 a0 = *(const float4*)&o0[0], a1 = *(const float4*)&o0[4];
    float4 b0 = *(const float4*)&o1[0], b1 = *(const float4*)&o1[4];
    float c[8];
    c[0] = a0.x - lam * b0.x; c[1] = a0.y - lam * b0.y;
    c[2] = a0.z - lam * b0.z; c[3] = a0.w - lam * b0.w;
    c[4] = a1.x - lam * b1.x; c[5] = a1.y - lam * b1.y;
    c[6] = a1.z - lam * b1.z; c[7] = a1.w - lam * b1.w;
    float ss = 0.f;
    #pragma unroll
    for (int i = 0; i < 8; i++) ss += c[i] * c[i];
    ss += __shfl_xor_sync(~0u, ss, 8);
    ss += __shfl_xor_sync(~0u, ss, 4);
    ss += __shfl_xor_sync(~0u, ss, 2);
    ss += __shfl_xor_sync(~0u, ss, 1);
    float rinv = rsqrtf(ss * (1.0f / 128.0f) + 1e-5f) * 0.6444909324090307f;

    uint32_t hv[4], lv[4];
    #pragma unroll
    for (int i = 0; i < 4; i++) {
        float v0 = c[2 * i] * rinv * subln[d + 2 * i];
        float v1 = c[2 * i + 1] * rinv * subln[d + 2 * i + 1];
        uint32_t hb;
        PACK_BF16X2(hb, v1, v0);
        float f0 = __int_as_float(hb << 16);
        float f1 = __int_as_float(hb & 0xFFFF0000u);
        uint32_t lb;
        PACK_BF16X2(lb, v1 - f1, v0 - f0);
        hv[i] = hb;
        lv[i] = lb;
    }
    size_t off = (size_t)t * 2048 + p * 128 + d;
    *(uint4*)(g_ath + off) = make_uint4(hv[0], hv[1], hv[2], hv[3]);
    *(uint4*)(g_atl + off) = make_uint4(lv[0], lv[1], lv[2], lv[3]);
}

// ---------------- launch ----------------
extern "C" void kernel_launch(void* const* d_in, const int* in_sizes, int n_in,
                              void* d_out, int out_size) {
    (void)in_sizes; (void)n_in; (void)out_size;
    const float* x     = (const float*)d_in[0];
    const float* cosb  = (const float*)d_in[1];
    const float* sinb  = (const float*)d_in[2];
    const float* Wq    = (const float*)d_in[3];
    const float* Wk    = (const float*)d_in[4];
    const float* Wv    = (const float*)d_in[5];
    const float* Wo    = (const float*)d_in[6];
    const float* lq1   = (const float*)d_in[7];
    const float* lk1   = (const float*)d_in[8];
    const float* lq2   = (const float*)d_in[9];
    const float* lk2   = (const float*)d_in[10];
    const float* subln = (const float*)d_in[11];
    float* out = (float*)d_out;

    float* vp;
    __nv_bfloat16 *xh, *xl, *wqh, *wql, *wkh, *wkl, *wvh, *wvl, *woh, *wol, *vhh, *vll;
    cudaGetSymbolAddress((void**)&vp, g_v);
    cudaGetSymbolAddress((void**)&xh, g_xh);   cudaGetSymbolAddress((void**)&xl, g_xl);
    cudaGetSymbolAddress((void**)&wqh, g_wqh); cudaGetSymbolAddress((void**)&wql, g_wql);
    cudaGetSymbolAddress((void**)&wkh, g_wkh); cudaGetSymbolAddress((void**)&wkl, g_wkl);
    cudaGetSymbolAddress((void**)&wvh, g_wvh); cudaGetSymbolAddress((void**)&wvl, g_wvl);
    cudaGetSymbolAddress((void**)&woh, g_woh); cudaGetSymbolAddress((void**)&wol, g_wol);
    cudaGetSymbolAddress((void**)&vhh, g_vh);  cudaGetSymbolAddress((void**)&vll, g_vl);

    cudaFuncSetAttribute(gemm_qkv, cudaFuncAttributeMaxDynamicSharedMemorySize, GEMM_SMEM);
    cudaFuncSetAttribute(gemm_wo,  cudaFuncAttributeMaxDynamicSharedMemorySize, GEMM_SMEM);
    cudaFuncSetAttribute(attn_hmma, cudaFuncAttributeMaxDynamicSharedMemorySize, AT_SMEM);

    const int SG = (TT * EE / 4) / 256;

    // Launch order chosen so ncu (-s 5 -c 1) captures gemm_qkv (launch index 5).
    lam_kernel<<<1, 32>>>(lq1, lk1, lq2, lk2);                       // 0
    split_kernel<<<SG, 256>>>((const float4*)x,  (uint2*)xh,  (uint2*)xl);   // 1
    split_kernel<<<SG, 256>>>((const float4*)Wq, (uint2*)wqh, (uint2*)wql);  // 2
    split_kernel<<<SG, 256>>>((const float4*)Wk, (uint2*)wkh, (uint2*)wkl);  // 3
    split_kernel<<<SG, 256>>>((const float4*)Wv, (uint2*)wvh, (uint2*)wvl);  // 4
    gemm_qkv<<<dim3(16, 16, 3), 256, GEMM_SMEM>>>(xh, xl);           // 5  <- ncu capture

    rope_split_kernel<<<8192, 256>>>(cosb, sinb);                    // 6
    split_kernel<<<SG, 256>>>((const float4*)vp, (uint2*)vhh, (uint2*)vll);  // 7
    split_kernel<<<SG, 256>>>((const float4*)Wo, (uint2*)woh, (uint2*)wol);  // 8

    attn_hmma<<<dim3(16, 32), 256, AT_SMEM>>>();                     // 9

    combine_kernel<<<TT, 256>>>(subln);                              // 10

    gemm_wo<<<dim3(16, 16), 256, GEMM_SMEM>>>(out);                  // 11
}